// round 11
// baseline (speedup 1.0000x reference)
#include <cuda_runtime.h>

typedef unsigned long long ull;

#define SEQ 12
#define DIM 10
#define H1 50
#define H2 10
#define TPB 128
#define ELEMS 4

// ---------- packed f32x2 with pure b64 carriers (1 SASS op each) ----------
__device__ __forceinline__ ull fma2u(ull a, ull b, ull c) {
    ull d; asm("fma.rn.f32x2 %0,%1,%2,%3;" : "=l"(d) : "l"(a), "l"(b), "l"(c)); return d;
}
__device__ __forceinline__ ull relu2(ull a) {
    ull d;
    asm("{\n\t.reg .f32 lo,hi;\n\tmov.b64 {lo,hi},%1;\n\t"
        "max.f32 lo,lo,0f00000000;\n\tmax.f32 hi,hi,0f00000000;\n\t"
        "mov.b64 %0,{lo,hi};\n\t}" : "=l"(d) : "l"(a));
    return d;
}
__device__ __forceinline__ ull pack2(float lo, float hi) {
    ull d; asm("mov.b64 %0,{%1,%2};" : "=l"(d) : "f"(lo), "f"(hi)); return d;
}
__device__ __forceinline__ float lo2(ull v) {
    float f; asm("{\n\t.reg .f32 h;\n\tmov.b64 {%0,h},%1;\n\t}" : "=f"(f) : "l"(v)); return f;
}
__device__ __forceinline__ float hi2(ull v) {
    float f; asm("{\n\t.reg .f32 l;\n\tmov.b64 {l,%0},%1;\n\t}" : "=f"(f) : "l"(v)); return f;
}
__device__ __forceinline__ float ex2a(float x) { float r; asm("ex2.approx.f32 %0, %1;" : "=f"(r) : "f"(x)); return r; }
__device__ __forceinline__ float lg2a(float x) { float r; asm("lg2.approx.f32 %0, %1;" : "=f"(r) : "f"(x)); return r; }

// Derived-weight math:
//   sc_s = k0*x_s + k1 ; k0 = A*t+Bc, k1 = C*t+Dc  (A..Dc weight-only)
//   pm_s = sc_s * (log2e/m), m = max sc ; mp = max pm = max(ml*iml, mn*iml)
//   e_s = exp2(pm_s - mp) ; E = sum e ; u = (sum e_s x_s)/E
//   mask_s = attn_s > mean(attn) <=> 12 e_s > E
//            <=> c0*x_s + (c1 - lg2E + log2 12) > 0   [affine in x_s]
//   h1_j = relu(P_j*t + Q_j*u + R_j) ;  tm = W3.relu(W2.h1 + b2) + b3

// Scalar attention phase for ONE element. Returns t, u; writes mask rows.
__device__ __forceinline__ void attn_elem(
    const float* __restrict__ inputs, const float* __restrict__ targets,
    float* __restrict__ out, int B, int write_mask, int b,
    float A, float Bc, float Cc, float Dc, float& t, float& u)
{
    const float L2E = 1.4426950408889634f;
    const float4* xi = (const float4*)(inputs + (size_t)b * SEQ);
    float4 a0 = xi[0], a1 = xi[1], a2 = xi[2];
    float x[SEQ] = {a0.x,a0.y,a0.z,a0.w, a1.x,a1.y,a1.z,a1.w, a2.x,a2.y,a2.z,a2.w};
    t = targets[b];

    const float k0 = fmaf(A, t, Bc);
    const float k1 = fmaf(Cc, t, Dc);

    // max & min of scores in one pass (min needed when 1/m < 0 flips order)
    float sc0 = fmaf(k0, x[0], k1);
    float ml = sc0, mn = sc0;
    #pragma unroll
    for (int s = 1; s < SEQ; s++) {
        float sc = fmaf(k0, x[s], k1);
        ml = fmaxf(ml, sc);
        mn = fminf(mn, sc);
    }
    const float iml = __fdividef(L2E, ml);          // log2e / m
    const float mp  = fmaxf(ml * iml, mn * iml);    // max of pm (linear extremes)
    const float c0  = k0 * iml;
    const float c1  = k1 * iml - mp;                // pm_s - mp = c0*x_s + c1

    float E = 0.f, U = 0.f;
    #pragma unroll
    for (int s = 0; s < SEQ; s++) {
        float e = ex2a(fmaf(c0, x[s], c1));
        E += e;
        U = fmaf(e, x[s], U);
    }
    u = U * __fdividef(1.0f, E);

    if (write_mask) {
        // mask_s <=> c0*x_s + (c1 - lg2E + log2 12) > 0
        const float cm = c1 - lg2a(E) + 3.5849625007211562f;
        float mv[SEQ];
        #pragma unroll
        for (int s = 0; s < SEQ; s++)
            mv[s] = (fmaf(c0, x[s], cm) > 0.f) ? 1.0f : 0.0f;
        float4* mo = (float4*)(out + B + (size_t)b * SEQ);
        mo[0] = make_float4(mv[0], mv[1], mv[2],  mv[3]);
        mo[1] = make_float4(mv[4], mv[5], mv[6],  mv[7]);
        mo[2] = make_float4(mv[8], mv[9], mv[10], mv[11]);
    }
}

__global__ __launch_bounds__(TPB, 7) void maskmodel_kernel(
    const float* __restrict__ inputs,   // [B, S, 1]
    const float* __restrict__ targets,  // [B, 1]
    const float* __restrict__ We_w, const float* __restrict__ We_b,
    const float* __restrict__ Wt_w, const float* __restrict__ Wt_b,
    const float* __restrict__ W1_w, const float* __restrict__ W1_b,
    const float* __restrict__ W2_w, const float* __restrict__ W2_b,
    const float* __restrict__ W3_w, const float* __restrict__ W3_b,
    float* __restrict__ out, int B, int write_mask)
{
    // pre-duplicated packed weights as u64 so LDS lands straight in b64 pairs
    __shared__ ulonglong2 sPQ[H1];          // {(P,P),(Q,Q)}
    __shared__ ull        sRR[H1];          // (R,R)
    __shared__ ulonglong2 sW2d[H1][H2/2];   // {(w_i,w_i),(w_{i+1},w_{i+1})}, w_i=W2[i][j]
    __shared__ ull        sW2bd[H2];        // (b2_i, b2_i)
    __shared__ ull        sW3d[H2];         // (w3_i, w3_i)
    __shared__ float      sK[5];            // A, Bc, C, Dc, W3_b

    const int tid = threadIdx.x;

    // ---- per-block derived-weight precompute ----
    if (tid < H1) {
        float p = 0.f, q = 0.f, r = W1_b[tid];
        #pragma unroll
        for (int i = 0; i < DIM; i++) {
            float w1a = W1_w[tid * 2 * DIM + i];
            float w1b = W1_w[tid * 2 * DIM + DIM + i];
            p = fmaf(w1a, Wt_w[i], p);
            q = fmaf(w1b, We_w[i], q);
            r = fmaf(w1a, Wt_b[i], fmaf(w1b, We_b[i], r));
        }
        sPQ[tid].x = pack2(p, p);
        sPQ[tid].y = pack2(q, q);
        sRR[tid]   = pack2(r, r);
    } else if (tid == H1) {
        float a = 0.f, bq = 0.f, c = 0.f, dd = 0.f;
        #pragma unroll
        for (int i = 0; i < DIM; i++) {
            a  = fmaf(We_w[i], Wt_w[i], a);
            bq = fmaf(We_w[i], Wt_b[i], bq);
            c  = fmaf(We_b[i], Wt_w[i], c);
            dd = fmaf(We_b[i], Wt_b[i], dd);
        }
        sK[0] = a; sK[1] = bq; sK[2] = c; sK[3] = dd; sK[4] = W3_b[0];
    }
    for (int k = tid; k < H1 * H2; k += TPB) {
        int j = k / H2, i = k % H2;
        float w = W2_w[i * H1 + j];             // W2 is [10,50] row-major
        ((ull*)sW2d)[j * H2 + i] = pack2(w, w);
    }
    if (tid < H2) {
        sW2bd[tid] = pack2(W2_b[tid], W2_b[tid]);
        sW3d[tid]  = pack2(W3_w[tid], W3_w[tid]);
    }
    __syncthreads();

    const float A  = sK[0], Bc = sK[1], Cc = sK[2], Dc = sK[3], W3b = sK[4];

    const int total = gridDim.x * TPB;          // elements per quarter
    const int b0 = blockIdx.x * TPB + tid;
    if (b0 >= B) return;
    const int b1 = b0 + total, b2 = b0 + 2 * total, b3 = b0 + 3 * total;
    const bool v1 = (b1 < B), v2 = (b2 < B), v3 = (b3 < B);

    // ---- scalar attention phases (arrays reused across calls) ----
    float t0, u0, t1 = 0.f, u1 = 0.f, t2 = 0.f, u2 = 0.f, t3 = 0.f, u3 = 0.f;
    attn_elem(inputs, targets, out, B, write_mask, b0, A, Bc, Cc, Dc, t0, u0);
    if (v1) attn_elem(inputs, targets, out, B, write_mask, b1, A, Bc, Cc, Dc, t1, u1);
    if (v2) attn_elem(inputs, targets, out, B, write_mask, b2, A, Bc, Cc, Dc, t2, u2);
    if (v3) attn_elem(inputs, targets, out, B, write_mask, b3, A, Bc, Cc, Dc, t3, u3);

    const ull ttA = pack2(t0, t1), uuA = pack2(u0, u1);
    const ull ttB = pack2(t2, t3), uuB = pack2(u2, u3);

    // ---- fused h1 -> W2 hot loop (all-packed u64 flow, LDS shared by 4 elems) ----
    ull accA[H2], accB[H2];
    #pragma unroll
    for (int i = 0; i < H2; i++) { accA[i] = sW2bd[i]; accB[i] = sW2bd[i]; }
    #pragma unroll 5
    for (int j = 0; j < H1; j++) {
        ulonglong2 pq = sPQ[j];                 // LDS.128 broadcast
        ull rr = sRR[j];                        // LDS.64 broadcast
        ull hA = fma2u(pq.y, uuA, rr);          // Q*u + R
        hA = fma2u(pq.x, ttA, hA);              // + P*t
        hA = relu2(hA);
        ull hB = fma2u(pq.y, uuB, rr);
        hB = fma2u(pq.x, ttB, hB);
        hB = relu2(hB);
        #pragma unroll
        for (int q = 0; q < H2 / 2; q++) {
            ulonglong2 w = sW2d[j][q];          // LDS.128 -> two b64 pairs
            accA[2*q]   = fma2u(w.x, hA, accA[2*q]);
            accA[2*q+1] = fma2u(w.y, hA, accA[2*q+1]);
            accB[2*q]   = fma2u(w.x, hB, accB[2*q]);
            accB[2*q+1] = fma2u(w.y, hB, accB[2*q+1]);
        }
    }

    // ---- W3 epilogue (packed: tmA=(tm0,tm1), tmB=(tm2,tm3)) ----
    ull tmA = pack2(W3b, W3b), tmB = pack2(W3b, W3b);
    #pragma unroll
    for (int i = 0; i < H2; i++) {
        ull w3 = sW3d[i];
        tmA = fma2u(w3, relu2(accA[i]), tmA);
        tmB = fma2u(w3, relu2(accB[i]), tmB);
    }
    out[b0] = lo2(tmA);
    if (v1) out[b1] = hi2(tmA);
    if (v2) out[b2] = lo2(tmB);
    if (v3) out[b3] = hi2(tmB);
}

extern "C" void kernel_launch(void* const* d_in, const int* in_sizes, int n_in,
                              void* d_out, int out_size) {
    const float* inputs  = (const float*)d_in[0];
    const float* targets = (const float*)d_in[1];
    const float* We_w    = (const float*)d_in[2];
    const float* We_b    = (const float*)d_in[3];
    const float* Wt_w    = (const float*)d_in[4];
    const float* Wt_b    = (const float*)d_in[5];
    const float* W1_w    = (const float*)d_in[6];
    const float* W1_b    = (const float*)d_in[7];
    const float* W2_w    = (const float*)d_in[8];
    const float* W2_b    = (const float*)d_in[9];
    const float* W3_w    = (const float*)d_in[10];
    const float* W3_b    = (const float*)d_in[11];
    float* out = (float*)d_out;

    const int B = in_sizes[1];
    const int write_mask = (out_size >= B * (1 + SEQ)) ? 1 : 0;
    const int blocks = (B + ELEMS * TPB - 1) / (ELEMS * TPB);

    maskmodel_kernel<<<blocks, TPB>>>(inputs, targets,
                                      We_w, We_b, Wt_w, Wt_b,
                                      W1_w, W1_b, W2_w, W2_b, W3_w, W3_b,
                                      out, B, write_mask);
}